// round 15
// baseline (speedup 1.0000x reference)
#include <cuda_runtime.h>
#include <cstdint>

// ---------------------------------------------------------------------------
// CustomFlashAttention — round 15
//   GEMMs: unchanged (R14 double-buffered FFMA2 gemm_tn; ceiling-bound).
//   Attention: d-split design — 512 threads, two 256-thread halves each
//     accumulate half of the head dim with the R13-proven 8x4 micro-tile.
//     Keeps per-warp K-tile traffic at the 8-warp level (L1 fix) while
//     doubling the warps available to hide latency (issue fix).
// ---------------------------------------------------------------------------

#define SEQ     2048
#define DMODEL  2048
#define NHEADS  16
#define HDIM    128

__device__ float g_Q[SEQ * DMODEL];
__device__ float g_K[SEQ * DMODEL];
__device__ float g_V[SEQ * DMODEL];
__device__ float g_O[SEQ * DMODEL];

typedef unsigned long long u64;

__device__ __forceinline__ u64 dup2(float x) {
    u64 r; asm("mov.b64 %0, {%1, %1};" : "=l"(r) : "f"(x)); return r;
}
__device__ __forceinline__ void ffma2(u64& d, u64 a, u64 b) {
    asm("fma.rn.f32x2 %0, %1, %2, %0;" : "+l"(d) : "l"(a), "l"(b));
}
__device__ __forceinline__ u64 fmul2(u64 a, u64 b) {
    u64 r; asm("mul.rn.f32x2 %0, %1, %2;" : "=l"(r) : "l"(a), "l"(b)); return r;
}
union F4 { float4 f; u64 p[2]; float s[4]; };

// ---------------------------------------------------------------------------
// GEMM: C[M,N] = A[M,K] @ B[N,K]^T (row-major). 128x128 tile, BK=16,
// 256 threads, 8x8 micro-tile, double-buffered smem. (R14, unchanged.)
// ---------------------------------------------------------------------------
#define BM 128
#define BN 128
#define BK 16
#define GT 256

__global__ void __launch_bounds__(GT, 2) gemm_tn_kernel(
    const float* __restrict__ A, const float* __restrict__ B,
    float* __restrict__ C, int M, int N, int K)
{
    __shared__ float As[2][BK][BM];
    __shared__ float Bs[2][BK][BN];

    const int t  = threadIdx.x;
    const int tx = t & 15;
    const int ty = t >> 4;
    const int m0 = blockIdx.y * BM;
    const int n0 = blockIdx.x * BN;

    u64 acc[8][4];
#pragma unroll
    for (int r = 0; r < 8; r++)
#pragma unroll
        for (int c = 0; c < 4; c++) acc[r][c] = 0ULL;

    const int nkt = K / BK;
    const int row = t >> 2;
    const int kq  = t & 3;

    float4 ra[2], rb[2];

#pragma unroll
    for (int i = 0; i < 2; i++) {
        int rr = row + i * 64;
        float4 va = *(const float4*)(A + (size_t)(m0 + rr) * K + kq * 4);
        float4 vb = *(const float4*)(B + (size_t)(n0 + rr) * K + kq * 4);
        As[0][kq * 4 + 0][rr] = va.x; As[0][kq * 4 + 1][rr] = va.y;
        As[0][kq * 4 + 2][rr] = va.z; As[0][kq * 4 + 3][rr] = va.w;
        Bs[0][kq * 4 + 0][rr] = vb.x; Bs[0][kq * 4 + 1][rr] = vb.y;
        Bs[0][kq * 4 + 2][rr] = vb.z; Bs[0][kq * 4 + 3][rr] = vb.w;
    }
    if (nkt > 1) {
#pragma unroll
        for (int i = 0; i < 2; i++) {
            int rr = row + i * 64;
            ra[i] = *(const float4*)(A + (size_t)(m0 + rr) * K + BK + kq * 4);
            rb[i] = *(const float4*)(B + (size_t)(n0 + rr) * K + BK + kq * 4);
        }
    }
    __syncthreads();

    for (int kt = 0; kt < nkt; kt++) {
        const int cur = kt & 1;
        if (kt + 1 < nkt) {
            const int nxt = cur ^ 1;
#pragma unroll
            for (int i = 0; i < 2; i++) {
                int rr = row + i * 64;
                As[nxt][kq * 4 + 0][rr] = ra[i].x; As[nxt][kq * 4 + 1][rr] = ra[i].y;
                As[nxt][kq * 4 + 2][rr] = ra[i].z; As[nxt][kq * 4 + 3][rr] = ra[i].w;
                Bs[nxt][kq * 4 + 0][rr] = rb[i].x; Bs[nxt][kq * 4 + 1][rr] = rb[i].y;
                Bs[nxt][kq * 4 + 2][rr] = rb[i].z; Bs[nxt][kq * 4 + 3][rr] = rb[i].w;
            }
        }
        if (kt + 2 < nkt) {
            int k0 = (kt + 2) * BK;
#pragma unroll
            for (int i = 0; i < 2; i++) {
                int rr = row + i * 64;
                ra[i] = *(const float4*)(A + (size_t)(m0 + rr) * K + k0 + kq * 4);
                rb[i] = *(const float4*)(B + (size_t)(n0 + rr) * K + k0 + kq * 4);
            }
        }
#pragma unroll
        for (int kk = 0; kk < BK; kk++) {
            float4 a0 = *(const float4*)&As[cur][kk][ty * 8];
            float4 a1 = *(const float4*)&As[cur][kk][ty * 8 + 4];
            const u64* bp = (const u64*)&Bs[cur][kk][tx * 8];
            u64 b0 = bp[0], b1 = bp[1], b2 = bp[2], b3 = bp[3];
            u64 ad[8];
            ad[0] = dup2(a0.x); ad[1] = dup2(a0.y);
            ad[2] = dup2(a0.z); ad[3] = dup2(a0.w);
            ad[4] = dup2(a1.x); ad[5] = dup2(a1.y);
            ad[6] = dup2(a1.z); ad[7] = dup2(a1.w);
#pragma unroll
            for (int r = 0; r < 8; r++) {
                ffma2(acc[r][0], ad[r], b0);
                ffma2(acc[r][1], ad[r], b1);
                ffma2(acc[r][2], ad[r], b2);
                ffma2(acc[r][3], ad[r], b3);
            }
        }
        __syncthreads();
    }

#pragma unroll
    for (int r = 0; r < 8; r++) {
        float* crow = C + (size_t)(m0 + ty * 8 + r) * N + n0 + tx * 8;
#pragma unroll
        for (int c = 0; c < 4; c++) {
            *(u64*)(crow + c * 2) = acc[r][c];
        }
    }
}

// ---------------------------------------------------------------------------
// Flash attention, d-split: 512 threads, halves own d[0,64)/d[64,128).
// One block per (128-query tile, head). 8 rows x 4 keys per thread.
// ---------------------------------------------------------------------------
#define BQ   128
#define BKT  64
#define AT   512
#define SLD  66

#define AOFF_Q  0
#define AOFF_K  (AOFF_Q + BQ * 128)
#define AOFF_V  (AOFF_K + BKT * 128)
#define AOFF_S0 (AOFF_V + BKT * 128)
#define AOFF_S1 (AOFF_S0 + BQ * SLD)
#define AOFF_M  (AOFF_S1 + BQ * SLD)
#define AOFF_L  (AOFF_M + BQ)
#define AOFF_F  (AOFF_L + BQ)
#define ATTN_SMEM ((AOFF_F + BQ) * 4)

__device__ __forceinline__ int qk_word(int row, int g) {
    return row * 128 + (((g ^ (row & 7)) & 31) << 2);
}

__global__ void __launch_bounds__(AT, 1) attn_kernel(
    const float* __restrict__ Q, const float* __restrict__ K,
    const float* __restrict__ V, float* __restrict__ O)
{
    extern __shared__ float sm[];
    float* Qs    = sm + AOFF_Q;
    float* Ks    = sm + AOFF_K;
    float* Vs    = sm + AOFF_V;
    float* Ss0   = sm + AOFF_S0;
    float* Ss1   = sm + AOFF_S1;
    float* row_m = sm + AOFF_M;
    float* row_l = sm + AOFF_L;
    float* row_f = sm + AOFF_F;

    const int t    = threadIdx.x;
    const int tx   = t & 15;
    const int ty   = (t >> 4) & 15;    // 0..15: row group
    const int dh   = t >> 8;           // 0/1: d-half
    const int q0   = blockIdx.x * BQ;
    const int hoff = blockIdx.y * HDIM;

    const int r0 = ty * 8;             // phase-2 rows
    const int dx = t & 31;             // phase-3 d-group
    const int r3 = (t >> 5) * 8;       // phase-3 rows

    // stage Q tile (swizzled), once
#pragma unroll
    for (int i = 0; i < 8; i++) {
        int p = t + i * AT;            // 0..4095
        int row = p >> 5, g = p & 31;
        float4 v = *(const float4*)(Q + (size_t)(q0 + row) * DMODEL + hoff + g * 4);
        *(float4*)&Qs[qk_word(row, g)] = v;
    }
    if (t < BQ) { row_m[t] = -1e30f; row_l[t] = 0.0f; }

    float* Sw = dh ? Ss1 : Ss0;

    u64 oa[8][2];                      // O accum: 4 d-floats per row
#pragma unroll
    for (int i = 0; i < 8; i++) { oa[i][0] = 0ULL; oa[i][1] = 0ULL; }

    const float scale = 0.0883883476483184406f;  // 1/sqrt(128)

    for (int kt = 0; kt < SEQ / BKT; kt++) {
        const int kbase = kt * BKT;
        __syncthreads();               // prev phase-3 done with Ks/Vs/Ss0

        // stage K (swizzled) + V (natural)
#pragma unroll
        for (int i = 0; i < 4; i++) {
            int p = t + i * AT;        // 0..2047
            int row = p >> 5, g = p & 31;
            float4 kv = *(const float4*)(K + (size_t)(kbase + row) * DMODEL + hoff + g * 4);
            *(float4*)&Ks[qk_word(row, g)] = kv;
            float4 vv = *(const float4*)(V + (size_t)(kbase + row) * DMODEL + hoff + g * 4);
            *(float4*)&Vs[row * 128 + g * 4] = vv;
        }
        __syncthreads();

        // phase 2: partial S over this thread's d-half, 8 rows x 4 keys
        {
            u64 sacc[8][4];
#pragma unroll
            for (int i = 0; i < 8; i++)
#pragma unroll
                for (int jj = 0; jj < 4; jj++) sacc[i][jj] = 0ULL;

#pragma unroll 4
            for (int gg = 0; gg < 16; gg++) {
                const int g = dh * 16 + gg;
                F4 kb[4];
#pragma unroll
                for (int jj = 0; jj < 4; jj++) {
                    int j = tx + 16 * jj;
                    kb[jj].f = *(const float4*)&Ks[j * 128 + (((g ^ (tx & 7)) & 31) << 2)];
                }
#pragma unroll
                for (int i = 0; i < 8; i++) {
                    F4 qa;
                    qa.f = *(const float4*)&Qs[(r0 + i) * 128 + (((g ^ i) & 31) << 2)];
#pragma unroll
                    for (int jj = 0; jj < 4; jj++) {
                        ffma2(sacc[i][jj], qa.p[0], kb[jj].p[0]);
                        ffma2(sacc[i][jj], qa.p[1], kb[jj].p[1]);
                    }
                }
            }
#pragma unroll
            for (int i = 0; i < 8; i++)
#pragma unroll
                for (int jj = 0; jj < 4; jj++) {
                    F4 a; a.p[0] = sacc[i][jj];
                    Sw[(r0 + i) * SLD + tx + 16 * jj] = (a.s[0] + a.s[1]) * scale;
                }
        }
        __syncthreads();

        // softmax: 4 threads per row, 16 scores each (sum the two partials)
        {
            const int row = t >> 2;
            const int qd  = t & 3;
            float* s0 = &Ss0[row * SLD + qd * 16];
            float* s1 = &Ss1[row * SLD + qd * 16];
            float v[16];
            float mloc = -1e30f;
#pragma unroll
            for (int j = 0; j < 16; j++) {
                v[j] = s0[j] + s1[j];
                mloc = fmaxf(mloc, v[j]);
            }
            mloc = fmaxf(mloc, __shfl_xor_sync(0xffffffffu, mloc, 1));
            mloc = fmaxf(mloc, __shfl_xor_sync(0xffffffffu, mloc, 2));
            const float mold = row_m[row];
            const float mnew = fmaxf(mold, mloc);
            float lloc = 0.0f;
#pragma unroll
            for (int j = 0; j < 16; j++) {
                float p = __expf(v[j] - mnew);
                s0[j] = p;
                lloc += p;
            }
            lloc += __shfl_xor_sync(0xffffffffu, lloc, 1);
            lloc += __shfl_xor_sync(0xffffffffu, lloc, 2);
            if (qd == 0) {
                float f = __expf(mold - mnew);
                row_f[row] = f;
                row_l[row] = row_l[row] * f + lloc;
                row_m[row] = mnew;
            }
        }
        __syncthreads();

        // phase 3: O = O*f + P V.  Thread: rows r3..r3+7, d 4*dx..4*dx+3.
        // V loads lane-consecutive (conflict-free); P loads warp-broadcast.
        {
#pragma unroll
            for (int i = 0; i < 8; i++) {
                u64 fd = dup2(row_f[r3 + i]);
                oa[i][0] = fmul2(oa[i][0], fd);
                oa[i][1] = fmul2(oa[i][1], fd);
            }
#pragma unroll 4
            for (int j = 0; j < BKT; j++) {
                F4 va;
                va.f = *(const float4*)&Vs[j * 128 + 4 * dx];
#pragma unroll
                for (int i = 0; i < 8; i++) {
                    u64 pd = dup2(Ss0[(r3 + i) * SLD + j]);
                    ffma2(oa[i][0], pd, va.p[0]);
                    ffma2(oa[i][1], pd, va.p[1]);
                }
            }
        }
    }

    // normalize and store
#pragma unroll
    for (int i = 0; i < 8; i++) {
        u64 inv = dup2(1.0f / row_l[r3 + i]);
        float* orow = O + (size_t)(q0 + r3 + i) * DMODEL + hoff + 4 * dx;
        F4 w;
        w.p[0] = fmul2(oa[i][0], inv);
        w.p[1] = fmul2(oa[i][1], inv);
        *(float4*)orow = w.f;
    }
}

// ---------------------------------------------------------------------------
// Launch
// ---------------------------------------------------------------------------
extern "C" void kernel_launch(void* const* d_in, const int* in_sizes, int n_in,
                              void* d_out, int out_size)
{
    (void)in_sizes; (void)n_in; (void)out_size;

    const float* x  = (const float*)d_in[0];
    const float* wq = (const float*)d_in[1];
    const float* wk = (const float*)d_in[2];
    const float* wv = (const float*)d_in[3];
    const float* wo = (const float*)d_in[4];
    float* out = (float*)d_out;

    float *pQ, *pK, *pV, *pO;
    cudaGetSymbolAddress((void**)&pQ, g_Q);
    cudaGetSymbolAddress((void**)&pK, g_K);
    cudaGetSymbolAddress((void**)&pV, g_V);
    cudaGetSymbolAddress((void**)&pO, g_O);

    cudaFuncSetAttribute(attn_kernel,
                         cudaFuncAttributeMaxDynamicSharedMemorySize, ATTN_SMEM);

    dim3 gg(DMODEL / BN, SEQ / BM);
    gemm_tn_kernel<<<gg, GT>>>(x, wq, pQ, SEQ, DMODEL, DMODEL);
    gemm_tn_kernel<<<gg, GT>>>(x, wk, pK, SEQ, DMODEL, DMODEL);
    gemm_tn_kernel<<<gg, GT>>>(x, wv, pV, SEQ, DMODEL, DMODEL);

    attn_kernel<<<dim3(SEQ / BQ, NHEADS), AT, ATTN_SMEM>>>(pQ, pK, pV, pO);

    gemm_tn_kernel<<<gg, GT>>>(pO, wo, out, SEQ, DMODEL, DMODEL);
}